// round 9
// baseline (speedup 1.0000x reference)
#include <cuda_runtime.h>
#include <cuda.h>
#include <cuda_fp16.h>
#include <cstdint>

// Problem constants
#define OUT_F   11008
#define IN_F    4096
#define NGROUPS 32
#define M_TOT   8192        // 4 * 2048

// ---------------------------------------------------------------------------
// tcgen05 is arch-specific; guard so the plain compute_103/sm_103 pass
// compiles empty bodies (R7 proved the sm_103a image is what executes).
// ---------------------------------------------------------------------------
#if defined(__CUDA_ARCH__) && (defined(__CUDA_ARCH_FEAT_SM103_ALL) || \
                               defined(__CUDA_ARCH_FEAT_SM100_ALL) || \
                               defined(__CUDA_ARCH_SPECIFIC__)     || \
                               defined(__CUDA_ARCH_FAMILY_SPECIFIC__))
#define HAS_TCGEN05 1
#else
#define HAS_TCGEN05 0
#endif

// Scratch (device globals — allocation-free per harness rules)
__device__ __align__(16) __half        g_X16[(size_t)M_TOT * IN_F];        // 67 MB
__device__ __align__(16) unsigned char g_Wp [(size_t)OUT_F * (IN_F / 2)];  // 22.5 MB

// ---------------------------------------------------------------------------
// x fp32 -> fp16
// ---------------------------------------------------------------------------
__global__ void __launch_bounds__(256) xcvt_kernel(const float4* __restrict__ x) {
    int idx = blockIdx.x * 256 + threadIdx.x;      // exact: M_TOT*IN_F/4 threads
    float4 v = x[idx];
    __half2 h0 = __floats2half2_rn(v.x, v.y);
    __half2 h1 = __floats2half2_rn(v.z, v.w);
    uint2 u;
    u.x = reinterpret_cast<uint32_t&>(h0);
    u.y = reinterpret_cast<uint32_t&>(h1);
    *reinterpret_cast<uint2*>(&g_X16[(size_t)idx * 4]) = u;
}

// ---------------------------------------------------------------------------
// repack: int32-per-byte weight_packed -> dense uint8 nibble pairs (4x smaller)
// ---------------------------------------------------------------------------
__global__ void __launch_bounds__(256) repack_kernel(const int4* __restrict__ wp) {
    int idx = blockIdx.x * 256 + threadIdx.x;      // exact: OUT_F*2048/4 threads
    int4 p = wp[idx];
    uchar4 b;
    b.x = (unsigned char)p.x; b.y = (unsigned char)p.y;
    b.z = (unsigned char)p.z; b.w = (unsigned char)p.w;
    reinterpret_cast<uchar4*>(g_Wp)[idx] = b;
}

// ===========================================================================
// Fused tcgen05 GEMM with in-kernel int4 dequant
//   out[M,N] = X16[M,K] @ dequant(Wp)[N,K]^T, f32 accum in TMEM
// ===========================================================================
#define BM 128
#define BN 256
#define BKH 64              // K halves per stage (128 B rows, SW128)
#define BKB 32              // K packed bytes per row per stage
#define NSA 4               // A stages
#define NSP 4               // packed-B stages
#define NSH 3               // fp16-B stages
#define KT  (IN_F / BKH)    // 64
#define GEMM_THREADS 320    // warps 0-7 dequant(+epilogue 0-3), warp 8 TMA, warp 9 MMA

// SMEM byte offsets
#define SM_TMEMPTR 0
#define SM_AF(s)  (16 + (s) * 8)      // A full
#define SM_AE(s)  (48 + (s) * 8)      // A empty
#define SM_PF(s)  (80 + (s) * 8)      // packed full
#define SM_PE(s)  (112 + (s) * 8)     // packed empty
#define SM_HF(s)  (144 + (s) * 8)     // fp16 full
#define SM_HE(s)  (168 + (s) * 8)     // fp16 empty
#define SM_DONE   192
#define SM_A(s)   (1024 + (s) * 16384)                 // 4 x 16 KB
#define SM_BH(s)  (66560 + (s) * 32768)                // 3 x 32 KB (1024-aligned)
#define SM_BP(s)  (164864 + (s) * 8192)                // 4 x 8 KB (128-aligned for TMA)
#define SM_SC     197632                               // 16 KB half scales [g][row]
#define SMEM_TOTAL 214016                              // < 232448 cap

#define A_STAGE_BYTES  (BM * BKH * 2)   // 16384
#define BP_STAGE_BYTES (BN * BKB)       // 8192

// idesc: kind::f16, A/B fp16, D f32, M=128, N=128 (two MMAs cover BN=256)
#define IDESC 0x8200010u

#if HAS_TCGEN05
// SW128 K-major SMEM descriptor base: layout=SW128(2), version=1, SBO=64, LBO=1
#define DESC_BASE ((2ull << 61) | (1ull << 46) | (64ull << 32) | (1ull << 16))
__device__ __forceinline__ uint64_t make_desc(uint32_t addr) {
    return DESC_BASE | ((uint64_t)(addr >> 4) & 0x3FFFull);
}
__device__ __forceinline__ void mbar_init(uint32_t a, uint32_t cnt) {
    asm volatile("mbarrier.init.shared::cta.b64 [%0], %1;" :: "r"(a), "r"(cnt) : "memory");
}
__device__ __forceinline__ void mbar_expect_tx(uint32_t a, uint32_t bytes) {
    asm volatile("mbarrier.arrive.expect_tx.shared::cta.b64 _, [%0], %1;"
                 :: "r"(a), "r"(bytes) : "memory");
}
__device__ __forceinline__ void mbar_arrive(uint32_t a) {
    asm volatile("mbarrier.arrive.shared::cta.b64 _, [%0];" :: "r"(a) : "memory");
}
__device__ __forceinline__ void mbar_wait(uint32_t a, uint32_t parity) {
    asm volatile(
        "{\n\t.reg .pred P;\n\t"
        "W_%=:\n\t"
        "mbarrier.try_wait.parity.shared::cta.b64 P, [%0], %1, 0x989680;\n\t"
        "@P bra.uni D_%=;\n\t"
        "bra.uni W_%=;\n\t"
        "D_%=:\n\t}"
        :: "r"(a), "r"(parity) : "memory");
}
__device__ __forceinline__ void tma_2d(uint32_t dst, const CUtensorMap* m,
                                       int x, int y, uint32_t mbar) {
    asm volatile(
        "cp.async.bulk.tensor.2d.shared::cta.global.tile.mbarrier::complete_tx::bytes "
        "[%0], [%1, {%2, %3}], [%4];"
        :: "r"(dst), "l"(m), "r"(x), "r"(y), "r"(mbar) : "memory");
}
__device__ __forceinline__ void mma_f16_ss(uint32_t d, uint64_t ad, uint64_t bd,
                                           uint32_t en) {
    asm volatile(
        "{\n\t.reg .pred p;\n\t"
        "setp.ne.u32 p, %4, 0;\n\t"
        "tcgen05.mma.cta_group::1.kind::f16 [%0], %1, %2, %3, {%5, %5, %5, %5}, p;\n\t}"
        :: "r"(d), "l"(ad), "l"(bd), "r"(IDESC), "r"(en), "r"(0u) : "memory");
}
__device__ __forceinline__ void tc_commit(uint32_t mbar) {
    asm volatile(
        "tcgen05.commit.cta_group::1.mbarrier::arrive::one.shared::cluster.b64 [%0];"
        :: "r"(mbar) : "memory");
}
// one packed-nibble word (n_even | n_odd<<16, biased 0x6400) -> (p-1032)*s
// (1024+n) - 1032 = n-8 exactly (both ends fp16-exact), single rounding on *s
__device__ __forceinline__ uint32_t dq_pair(uint32_t qbits, __half2 s2) {
    uint32_t kb = 0x64086408u;  // half2(1032, 1032)
    __half2 k1032 = *reinterpret_cast<__half2*>(&kb);
    __half2 p = *reinterpret_cast<__half2*>(&qbits);
    __half2 r = __hmul2(__hsub2(p, k1032), s2);
    return *reinterpret_cast<uint32_t*>(&r);
}
#endif  // HAS_TCGEN05

__global__ void __launch_bounds__(GEMM_THREADS)
gemm_fused_kernel(const __grid_constant__ CUtensorMap tmA,
                  const __grid_constant__ CUtensorMap tmBp,
                  const float* __restrict__ scales,
                  float* __restrict__ out) {
#if HAS_TCGEN05
    extern __shared__ __align__(1024) char smem[];
    uint32_t sb = (uint32_t)__cvta_generic_to_shared(smem);
    const int tid  = threadIdx.x;
    const int wid  = tid >> 5;
    const int lane = tid & 31;
    const int m0 = blockIdx.x * BM;
    const int n0 = blockIdx.y * BN;

    if (tid == 0) {
#pragma unroll
        for (int s = 0; s < NSA; s++) { mbar_init(sb + SM_AF(s), 1); mbar_init(sb + SM_AE(s), 1); }
#pragma unroll
        for (int s = 0; s < NSP; s++) { mbar_init(sb + SM_PF(s), 1); mbar_init(sb + SM_PE(s), 8); }
#pragma unroll
        for (int s = 0; s < NSH; s++) { mbar_init(sb + SM_HF(s), 8); mbar_init(sb + SM_HE(s), 1); }
        mbar_init(sb + SM_DONE, 1);
    }
    if (wid == 9) {  // warp-collective TMEM alloc: 256 f32 cols for D
        asm volatile("tcgen05.alloc.cta_group::1.sync.aligned.shared::cta.b32 [%0], %1;"
                     :: "r"(sb + SM_TMEMPTR), "r"(256u) : "memory");
        asm volatile("tcgen05.relinquish_alloc_permit.cta_group::1.sync.aligned;");
    }
    __syncthreads();
    uint32_t tmem;
    asm volatile("ld.shared.b32 %0, [%1];" : "=r"(tmem) : "r"(sb + SM_TMEMPTR));

    if (wid == 8 && lane == 0) {
        // ---- TMA producer: A fp16 tiles + packed-B tiles (both rings depth 4) ----
        int pe = 1, s = 0;   // parity 1: empty-waits pass immediately on fresh barriers
        for (int kt = 0; kt < KT; kt++) {
            mbar_wait(sb + SM_AE(s), (uint32_t)pe);
            mbar_expect_tx(sb + SM_AF(s), A_STAGE_BYTES);
            tma_2d(sb + SM_A(s), &tmA, kt * BKH, m0, sb + SM_AF(s));
            mbar_wait(sb + SM_PE(s), (uint32_t)pe);
            mbar_expect_tx(sb + SM_PF(s), BP_STAGE_BYTES);
            tma_2d(sb + SM_BP(s), &tmBp, kt * BKB, n0, sb + SM_PF(s));
            if (++s == NSA) { s = 0; pe ^= 1; }
        }
    } else if (wid == 9 && lane == 0) {
        // ---- MMA issuer ----
        int pa = 0, ph = 0, sa = 0, sh = 0;
        for (int kt = 0; kt < KT; kt++) {
            mbar_wait(sb + SM_AF(sa), (uint32_t)pa);
            mbar_wait(sb + SM_HF(sh), (uint32_t)ph);
            uint64_t ad  = make_desc(sb + SM_A(sa));
            uint64_t bd0 = make_desc(sb + SM_BH(sh));
            uint64_t bd1 = bd0 + 1024;  // +16 KB = B rows 128..255
#pragma unroll
            for (int ks = 0; ks < 4; ks++) {
                uint32_t en = (kt | ks) ? 1u : 0u;
                mma_f16_ss(tmem,       ad + 2 * ks, bd0 + 2 * ks, en);
                mma_f16_ss(tmem + 128, ad + 2 * ks, bd1 + 2 * ks, en);
            }
            tc_commit(sb + SM_AE(sa));   // arrive-one when all prior MMAs drain
            tc_commit(sb + SM_HE(sh));
            if (++sa == NSA) { sa = 0; pa ^= 1; }
            if (++sh == NSH) { sh = 0; ph ^= 1; }
        }
        tc_commit(sb + SM_DONE);         // fires when ALL MMAs complete
    } else if (wid < 8) {
        // ---- dequant workers: thread r owns B row r (0..255) ----
        const int r = tid;
        // preload this row's 32 scales as half into SMEM [g][row]
        {
            const float4* srow = (const float4*)(scales + (size_t)(n0 + r) * NGROUPS);
#pragma unroll
            for (int j = 0; j < 8; j++) {
                float4 v = srow[j];
                __half h[4] = { __float2half_rn(v.x), __float2half_rn(v.y),
                                __float2half_rn(v.z), __float2half_rn(v.w) };
#pragma unroll
                for (int e = 0; e < 4; e++) {
                    uint16_t hb = *reinterpret_cast<uint16_t*>(&h[e]);
                    asm volatile("st.shared.u16 [%0], %1;"
                                 :: "r"(sb + SM_SC + (((4 * j + e) * 256 + r) * 2)), "h"(hb));
                }
            }
        }
        int pf = 0, pe_h = 1, sp = 0, sh = 0;
        const uint32_t xr = (uint32_t)(r & 7) << 4;   // SW128 chunk xor (bytes)
        for (int kt = 0; kt < KT; kt++) {
            mbar_wait(sb + SM_PF(sp), (uint32_t)pf);
            mbar_wait(sb + SM_HE(sh), (uint32_t)pe_h);
            // load 32 packed bytes (64 nibbles = this row's 64 halves for this stage)
            uint32_t pa_addr = sb + SM_BP(sp) + r * BKB;
            uint32_t w[8];
            asm volatile("ld.shared.v4.b32 {%0,%1,%2,%3}, [%4];"
                         : "=r"(w[0]), "=r"(w[1]), "=r"(w[2]), "=r"(w[3]) : "r"(pa_addr));
            asm volatile("ld.shared.v4.b32 {%0,%1,%2,%3}, [%4];"
                         : "=r"(w[4]), "=r"(w[5]), "=r"(w[6]), "=r"(w[7]) : "r"(pa_addr + 16));
            // per-group scale: group = kt>>1 (BKH=64 = half a 128-group)
            uint16_t sbits;
            asm volatile("ld.shared.u16 %0, [%1];"
                         : "=h"(sbits) : "r"(sb + SM_SC + (((kt >> 1) * 256 + r) * 2)));
            uint32_t s32 = (uint32_t)sbits | ((uint32_t)sbits << 16);
            __half2 s2 = *reinterpret_cast<__half2*>(&s32);
            // expand: word j -> 8 halves (K = 8j..8j+7) -> 16B chunk j (swizzled)
            uint32_t obase = sb + SM_BH(sh) + r * 128;
#pragma unroll
            for (int j = 0; j < 8; j++) {
                uint32_t v = w[j];
                uint32_t q0 = (v & 0x0000000Fu) | ((v << 12) & 0x000F0000u) | 0x64006400u;
                uint32_t q1 = ((v >> 8) & 0x0000000Fu) | ((v << 4) & 0x000F0000u) | 0x64006400u;
                uint32_t q2 = ((v >> 16) & 0x0000000Fu) | ((v >> 4) & 0x000F0000u) | 0x64006400u;
                uint32_t q3 = ((v >> 24) & 0x0000000Fu) | ((v >> 12) & 0x000F0000u) | 0x64006400u;
                uint32_t h0 = dq_pair(q0, s2), h1 = dq_pair(q1, s2);
                uint32_t h2 = dq_pair(q2, s2), h3 = dq_pair(q3, s2);
                asm volatile("st.shared.v4.b32 [%0], {%1,%2,%3,%4};"
                             :: "r"(obase + (((uint32_t)j << 4) ^ xr)),
                                "r"(h0), "r"(h1), "r"(h2), "r"(h3));
            }
            // make generic-proxy stores visible to tcgen05 (async proxy)
            asm volatile("fence.proxy.async.shared::cta;" ::: "memory");
            __syncwarp();
            if (lane == 0) {
                mbar_arrive(sb + SM_PE(sp));   // packed stage consumed
                mbar_arrive(sb + SM_HF(sh));   // fp16 stage ready
            }
            if (++sp == NSP) { sp = 0; pf ^= 1; }
            if (++sh == NSH) { sh = 0; pe_h ^= 1; }
        }
        // ---- epilogue: warps 0-3 read TMEM subpartitions, store f32 ----
        if (wid < 4) {
            mbar_wait(sb + SM_DONE, 0);
            asm volatile("tcgen05.fence::after_thread_sync;" ::: "memory");
            int row = m0 + wid * 32 + lane;
            float* orow = out + (size_t)row * OUT_F + n0;
#pragma unroll
            for (int ch = 0; ch < 8; ch++) {
                uint32_t rg[32];
                asm volatile(
                    "tcgen05.ld.sync.aligned.32x32b.x32.b32 "
                    "{%0, %1, %2, %3, %4, %5, %6, %7, "
                    " %8, %9, %10, %11, %12, %13, %14, %15, "
                    " %16, %17, %18, %19, %20, %21, %22, %23, "
                    " %24, %25, %26, %27, %28, %29, %30, %31}, [%32];"
                    : "=r"(rg[0]),  "=r"(rg[1]),  "=r"(rg[2]),  "=r"(rg[3]),
                      "=r"(rg[4]),  "=r"(rg[5]),  "=r"(rg[6]),  "=r"(rg[7]),
                      "=r"(rg[8]),  "=r"(rg[9]),  "=r"(rg[10]), "=r"(rg[11]),
                      "=r"(rg[12]), "=r"(rg[13]), "=r"(rg[14]), "=r"(rg[15]),
                      "=r"(rg[16]), "=r"(rg[17]), "=r"(rg[18]), "=r"(rg[19]),
                      "=r"(rg[20]), "=r"(rg[21]), "=r"(rg[22]), "=r"(rg[23]),
                      "=r"(rg[24]), "=r"(rg[25]), "=r"(rg[26]), "=r"(rg[27]),
                      "=r"(rg[28]), "=r"(rg[29]), "=r"(rg[30]), "=r"(rg[31])
                    : "r"(tmem + ch * 32));
                asm volatile("tcgen05.wait::ld.sync.aligned;" ::: "memory");
#pragma unroll
                for (int j = 0; j < 8; j++) {
                    float4 v = make_float4(__uint_as_float(rg[4 * j]),
                                           __uint_as_float(rg[4 * j + 1]),
                                           __uint_as_float(rg[4 * j + 2]),
                                           __uint_as_float(rg[4 * j + 3]));
                    *reinterpret_cast<float4*>(orow + ch * 32 + 4 * j) = v;
                }
            }
            asm volatile("tcgen05.fence::before_thread_sync;" ::: "memory");
        }
    }

    __syncthreads();
    if (wid == 9) {  // warp-collective dealloc
        asm volatile("tcgen05.dealloc.cta_group::1.sync.aligned.b32 %0, %1;"
                     :: "r"(tmem), "r"(256u));
    }
#endif  // HAS_TCGEN05
}

// ---------------------------------------------------------------------------
// Launch
// ---------------------------------------------------------------------------
typedef CUresult (CUDAAPI *PFN_encodeTiled_local)(
    CUtensorMap*, CUtensorMapDataType, cuuint32_t, void*,
    const cuuint64_t*, const cuuint64_t*, const cuuint32_t*, const cuuint32_t*,
    CUtensorMapInterleave, CUtensorMapSwizzle, CUtensorMapL2promotion,
    CUtensorMapFloatOOBfill);

extern "C" void kernel_launch(void* const* d_in, const int* in_sizes, int n_in,
                              void* d_out, int out_size) {
    const float* x      = (const float*)d_in[0];   // [4,2048,4096] fp32
    const int*   wp     = (const int*)d_in[1];     // [11008,2048] int32 (bytes)
    const float* scales = (const float*)d_in[2];   // [11008,32] fp32
    float* out = (float*)d_out;                    // [4,2048,11008] fp32

    // prep: x -> fp16; weight bytes -> dense 4-bit packed
    xcvt_kernel<<<(M_TOT * IN_F / 4) / 256, 256>>>((const float4*)x);
    repack_kernel<<<(OUT_F * (IN_F / 2) / 4) / 256, 256>>>((const int4*)wp);

    // tensormaps (driver entry point via runtime — no -lcuda link dependency)
    PFN_encodeTiled_local encode = nullptr;
    cudaDriverEntryPointQueryResult qres;
    cudaGetDriverEntryPoint("cuTensorMapEncodeTiled", (void**)&encode,
                            cudaEnableDefault, &qres);
    void *pX = nullptr, *pW = nullptr;
    cudaGetSymbolAddress(&pX, g_X16);
    cudaGetSymbolAddress(&pW, g_Wp);

    CUtensorMap tmA, tmBp;
    if (encode) {
        // A: fp16 [M_TOT, IN_F], SW128 boxes of 64 halves x 128 rows
        cuuint64_t dimsA[2] = {IN_F, M_TOT};
        cuuint64_t strA[1]  = {IN_F * 2};
        cuuint32_t boxA[2]  = {BKH, BM};
        cuuint32_t es[2]    = {1, 1};
        encode(&tmA, CU_TENSOR_MAP_DATA_TYPE_FLOAT16, 2, pX, dimsA, strA, boxA, es,
               CU_TENSOR_MAP_INTERLEAVE_NONE, CU_TENSOR_MAP_SWIZZLE_128B,
               CU_TENSOR_MAP_L2_PROMOTION_L2_128B, CU_TENSOR_MAP_FLOAT_OOB_FILL_NONE);
        // B packed: uint8 [OUT_F, IN_F/2], boxes of 32 bytes x 256 rows, no swizzle
        cuuint64_t dimsB[2] = {IN_F / 2, OUT_F};
        cuuint64_t strB[1]  = {IN_F / 2};
        cuuint32_t boxB[2]  = {BKB, BN};
        encode(&tmBp, CU_TENSOR_MAP_DATA_TYPE_UINT8, 2, pW, dimsB, strB, boxB, es,
               CU_TENSOR_MAP_INTERLEAVE_NONE, CU_TENSOR_MAP_SWIZZLE_NONE,
               CU_TENSOR_MAP_L2_PROMOTION_L2_128B, CU_TENSOR_MAP_FLOAT_OOB_FILL_NONE);
    }

    cudaFuncSetAttribute(gemm_fused_kernel, cudaFuncAttributeMaxDynamicSharedMemorySize,
                         SMEM_TOTAL);
    dim3 grid(M_TOT / BM, OUT_F / BN);   // (64, 43); m fastest -> B strip L2 reuse
    gemm_fused_kernel<<<grid, GEMM_THREADS, SMEM_TOTAL>>>(tmA, tmBp, scales, out);
}

// round 10
// speedup vs baseline: 1.3694x; 1.3694x over previous
#include <cuda_runtime.h>
#include <cuda.h>
#include <cuda_fp16.h>
#include <cstdint>

// Problem constants
#define OUT_F   11008
#define IN_F    4096
#define NGROUPS 32
#define M_TOT   8192        // 4 * 2048

// ---------------------------------------------------------------------------
// tcgen05 is arch-specific; guard so the plain compute_103/sm_103 pass
// compiles empty bodies (the sm_103a image is what executes, proven R7).
// ---------------------------------------------------------------------------
#if defined(__CUDA_ARCH__) && (defined(__CUDA_ARCH_FEAT_SM103_ALL) || \
                               defined(__CUDA_ARCH_FEAT_SM100_ALL) || \
                               defined(__CUDA_ARCH_SPECIFIC__)     || \
                               defined(__CUDA_ARCH_FAMILY_SPECIFIC__))
#define HAS_TCGEN05 1
#else
#define HAS_TCGEN05 0
#endif

// Scratch (device globals — allocation-free per harness rules)
__device__ __align__(16) __half g_W16[(size_t)OUT_F * IN_F];   // ~90 MB
__device__ __align__(16) __half g_X16[(size_t)M_TOT * IN_F];   // ~67 MB

// ---------------------------------------------------------------------------
// x fp32 -> fp16
// ---------------------------------------------------------------------------
__global__ void __launch_bounds__(256) xcvt_kernel(const float4* __restrict__ x) {
    int idx = blockIdx.x * 256 + threadIdx.x;      // exact: M_TOT*IN_F/4 threads
    float4 v = x[idx];
    __half2 h0 = __floats2half2_rn(v.x, v.y);
    __half2 h1 = __floats2half2_rn(v.z, v.w);
    uint2 u;
    u.x = reinterpret_cast<uint32_t&>(h0);
    u.y = reinterpret_cast<uint32_t&>(h1);
    *reinterpret_cast<uint2*>(&g_X16[(size_t)idx * 4]) = u;
}

// ---------------------------------------------------------------------------
// int4 dequant -> fp16 weights (unfused; DRAM-bound, ~30us)
// ---------------------------------------------------------------------------
__global__ void __launch_bounds__(256) dequant_kernel(const int4* __restrict__ wp,
                                                      const float* __restrict__ scales) {
    int idx = blockIdx.x * 256 + threadIdx.x;      // exact: OUT_F*(IN_F/2)/4 threads
    int4 p = wp[idx];
    int base = idx * 4;                            // packed-byte index
    int o = base >> 11;                            // / (IN_F/2 = 2048)
    int c = base & 2047;                           // packed col; output col i = 2c
    int g = c >> 6;                                // group = c/64 (same for all 8 outputs)
    float s = scales[o * NGROUPS + g];
    __align__(16) __half hs[8];
    int v[4] = {p.x, p.y, p.z, p.w};
#pragma unroll
    for (int j = 0; j < 4; j++) {
        int b = v[j] & 0xFF;
        hs[2 * j]     = __float2half_rn((float)((b & 15) - 8) * s);
        hs[2 * j + 1] = __float2half_rn((float)(((b >> 4) & 15) - 8) * s);
    }
    *reinterpret_cast<uint4*>(&g_W16[(size_t)o * IN_F + 2 * c]) = *reinterpret_cast<uint4*>(hs);
}

// ===========================================================================
// tcgen05 GEMM: out[M,N] = X16[M,K] @ W16[N,K]^T, f32 accum in TMEM
// BM=256 x BN=256 tile via 4 x (M128,N128) MMAs into a 512-col accumulator.
// ===========================================================================
#define BM 256
#define BN 256
#define BK 64               // halves per stage (128 B rows -> SW128)
#define NSTAGE 3
#define KTILES (IN_F / BK)  // 64
#define GEMM_THREADS 192    // warps 0-3 epilogue, warp 4 TMA, warp 5 MMA

// SMEM byte offsets
#define SM_TMEMPTR  0
#define SM_FULL(s)  (16 + (s) * 8)
#define SM_EMPTY(s) (48 + (s) * 8)
#define SM_DONE     80
#define SM_A(s)     (1024 + (s) * (BM * BK * 2))                          // 3 x 32 KB
#define SM_B(s)     (1024 + NSTAGE * (BM * BK * 2) + (s) * (BN * BK * 2)) // 3 x 32 KB
#define SMEM_TOTAL  (1024 + NSTAGE * (BM * BK + BN * BK) * 2)             // 197632 B
#define STAGE_BYTES ((BM + BN) * BK * 2)                                  // 65536

// idesc: kind::f16, A/B fp16 (0), D f32, M=128, N=128
#define IDESC 0x8200010u

#if HAS_TCGEN05
// SW128 K-major SMEM descriptor base: layout=SW128(2), version=1, SBO=64, LBO=1
#define DESC_BASE ((2ull << 61) | (1ull << 46) | (64ull << 32) | (1ull << 16))
__device__ __forceinline__ uint64_t make_desc(uint32_t addr) {
    return DESC_BASE | ((uint64_t)(addr >> 4) & 0x3FFFull);
}
__device__ __forceinline__ void mbar_init(uint32_t a, uint32_t cnt) {
    asm volatile("mbarrier.init.shared::cta.b64 [%0], %1;" :: "r"(a), "r"(cnt) : "memory");
}
__device__ __forceinline__ void mbar_expect_tx(uint32_t a, uint32_t bytes) {
    asm volatile("mbarrier.arrive.expect_tx.shared::cta.b64 _, [%0], %1;"
                 :: "r"(a), "r"(bytes) : "memory");
}
__device__ __forceinline__ void mbar_wait(uint32_t a, uint32_t parity) {
    asm volatile(
        "{\n\t.reg .pred P;\n\t"
        "W_%=:\n\t"
        "mbarrier.try_wait.parity.shared::cta.b64 P, [%0], %1, 0x989680;\n\t"
        "@P bra.uni D_%=;\n\t"
        "bra.uni W_%=;\n\t"
        "D_%=:\n\t}"
        :: "r"(a), "r"(parity) : "memory");
}
__device__ __forceinline__ void tma_2d(uint32_t dst, const CUtensorMap* m,
                                       int x, int y, uint32_t mbar) {
    asm volatile(
        "cp.async.bulk.tensor.2d.shared::cta.global.tile.mbarrier::complete_tx::bytes "
        "[%0], [%1, {%2, %3}], [%4];"
        :: "r"(dst), "l"(m), "r"(x), "r"(y), "r"(mbar) : "memory");
}
__device__ __forceinline__ void mma_f16_ss(uint32_t d, uint64_t ad, uint64_t bd,
                                           uint32_t en) {
    asm volatile(
        "{\n\t.reg .pred p;\n\t"
        "setp.ne.u32 p, %4, 0;\n\t"
        "tcgen05.mma.cta_group::1.kind::f16 [%0], %1, %2, %3, {%5, %5, %5, %5}, p;\n\t}"
        :: "r"(d), "l"(ad), "l"(bd), "r"(IDESC), "r"(en), "r"(0u) : "memory");
}
__device__ __forceinline__ void tc_commit(uint32_t mbar) {
    asm volatile(
        "tcgen05.commit.cta_group::1.mbarrier::arrive::one.shared::cluster.b64 [%0];"
        :: "r"(mbar) : "memory");
}
#endif  // HAS_TCGEN05

__global__ void __launch_bounds__(GEMM_THREADS)
gemm_tc_kernel(const __grid_constant__ CUtensorMap tmA,
               const __grid_constant__ CUtensorMap tmB,
               float* __restrict__ out) {
#if HAS_TCGEN05
    extern __shared__ __align__(1024) char smem[];
    uint32_t sbase = (uint32_t)__cvta_generic_to_shared(smem);
    const int tid = threadIdx.x;
    const int wid = tid >> 5;
    const int lane = tid & 31;
    const int m0 = blockIdx.x * BM;
    const int n0 = blockIdx.y * BN;

    if (tid == 0) {
#pragma unroll
        for (int s = 0; s < NSTAGE; s++) {
            mbar_init(sbase + SM_FULL(s), 1);
            mbar_init(sbase + SM_EMPTY(s), 1);
        }
        mbar_init(sbase + SM_DONE, 1);
    }
    if (wid == 5) {  // warp-collective TMEM alloc: full 512 f32 cols for D
        asm volatile("tcgen05.alloc.cta_group::1.sync.aligned.shared::cta.b32 [%0], %1;"
                     :: "r"(sbase + SM_TMEMPTR), "r"(512u) : "memory");
        asm volatile("tcgen05.relinquish_alloc_permit.cta_group::1.sync.aligned;");
    }
    __syncthreads();
    uint32_t tmem;
    asm volatile("ld.shared.b32 %0, [%1];" : "=r"(tmem) : "r"(sbase + SM_TMEMPTR));

    if (wid == 4 && lane == 0) {
        // ---- TMA producer ----
        int phase = 1, s = 0;  // parity 1: first empty-waits pass immediately
        for (int kt = 0; kt < KTILES; kt++) {
            mbar_wait(sbase + SM_EMPTY(s), (uint32_t)phase);
            mbar_expect_tx(sbase + SM_FULL(s), STAGE_BYTES);
            tma_2d(sbase + SM_A(s), &tmA, kt * BK, m0, sbase + SM_FULL(s));
            tma_2d(sbase + SM_B(s), &tmB, kt * BK, n0, sbase + SM_FULL(s));
            if (++s == NSTAGE) { s = 0; phase ^= 1; }
        }
    } else if (wid == 5 && lane == 0) {
        // ---- MMA issuer: 4 x (M128,N128) per k16 step ----
        int phase = 0, s = 0;
        for (int kt = 0; kt < KTILES; kt++) {
            mbar_wait(sbase + SM_FULL(s), (uint32_t)phase);
            uint64_t ad0 = make_desc(sbase + SM_A(s));
            uint64_t ad1 = ad0 + 1024;  // +16 KB = A rows 128..255
            uint64_t bd0 = make_desc(sbase + SM_B(s));
            uint64_t bd1 = bd0 + 1024;  // +16 KB = B rows 128..255
#pragma unroll
            for (int ks = 0; ks < 4; ks++) {   // 4 x k16 per BK=64 stage
                uint32_t en = (kt | ks) ? 1u : 0u;
                mma_f16_ss(tmem,       ad0 + 2 * ks, bd0 + 2 * ks, en);  // mh0 x nh0
                mma_f16_ss(tmem + 128, ad0 + 2 * ks, bd1 + 2 * ks, en);  // mh0 x nh1
                mma_f16_ss(tmem + 256, ad1 + 2 * ks, bd0 + 2 * ks, en);  // mh1 x nh0
                mma_f16_ss(tmem + 384, ad1 + 2 * ks, bd1 + 2 * ks, en);  // mh1 x nh1
            }
            tc_commit(sbase + SM_EMPTY(s));    // stage reusable once MMAs drained
            if (++s == NSTAGE) { s = 0; phase ^= 1; }
        }
        tc_commit(sbase + SM_DONE);            // fires when ALL MMAs complete
    } else if (wid < 4) {
        // ---- epilogue: 2 output rows per lane (one per M-half) ----
        mbar_wait(sbase + SM_DONE, 0);
        asm volatile("tcgen05.fence::after_thread_sync;" ::: "memory");
#pragma unroll
        for (int mh = 0; mh < 2; mh++) {
            int row = m0 + mh * 128 + wid * 32 + lane;
            float* orow = out + (size_t)row * OUT_F + n0;
#pragma unroll
            for (int ch = 0; ch < 8; ch++) {   // 8 x 32 cols = 256 per M-half
                uint32_t r[32];
                asm volatile(
                    "tcgen05.ld.sync.aligned.32x32b.x32.b32 "
                    "{%0, %1, %2, %3, %4, %5, %6, %7, "
                    " %8, %9, %10, %11, %12, %13, %14, %15, "
                    " %16, %17, %18, %19, %20, %21, %22, %23, "
                    " %24, %25, %26, %27, %28, %29, %30, %31}, [%32];"
                    : "=r"(r[0]),  "=r"(r[1]),  "=r"(r[2]),  "=r"(r[3]),
                      "=r"(r[4]),  "=r"(r[5]),  "=r"(r[6]),  "=r"(r[7]),
                      "=r"(r[8]),  "=r"(r[9]),  "=r"(r[10]), "=r"(r[11]),
                      "=r"(r[12]), "=r"(r[13]), "=r"(r[14]), "=r"(r[15]),
                      "=r"(r[16]), "=r"(r[17]), "=r"(r[18]), "=r"(r[19]),
                      "=r"(r[20]), "=r"(r[21]), "=r"(r[22]), "=r"(r[23]),
                      "=r"(r[24]), "=r"(r[25]), "=r"(r[26]), "=r"(r[27]),
                      "=r"(r[28]), "=r"(r[29]), "=r"(r[30]), "=r"(r[31])
                    : "r"(tmem + mh * 256 + ch * 32));
                asm volatile("tcgen05.wait::ld.sync.aligned;" ::: "memory");
#pragma unroll
                for (int j = 0; j < 8; j++) {
                    float4 v = make_float4(__uint_as_float(r[4 * j]),
                                           __uint_as_float(r[4 * j + 1]),
                                           __uint_as_float(r[4 * j + 2]),
                                           __uint_as_float(r[4 * j + 3]));
                    *reinterpret_cast<float4*>(orow + ch * 32 + 4 * j) = v;
                }
            }
        }
        asm volatile("tcgen05.fence::before_thread_sync;" ::: "memory");
    }

    __syncthreads();
    if (wid == 5) {  // warp-collective dealloc
        asm volatile("tcgen05.dealloc.cta_group::1.sync.aligned.b32 %0, %1;"
                     :: "r"(tmem), "r"(512u));
    }
#endif  // HAS_TCGEN05
}

// ---------------------------------------------------------------------------
// Launch
// ---------------------------------------------------------------------------
typedef CUresult (CUDAAPI *PFN_encodeTiled_local)(
    CUtensorMap*, CUtensorMapDataType, cuuint32_t, void*,
    const cuuint64_t*, const cuuint64_t*, const cuuint32_t*, const cuuint32_t*,
    CUtensorMapInterleave, CUtensorMapSwizzle, CUtensorMapL2promotion,
    CUtensorMapFloatOOBfill);

extern "C" void kernel_launch(void* const* d_in, const int* in_sizes, int n_in,
                              void* d_out, int out_size) {
    const float* x      = (const float*)d_in[0];   // [4,2048,4096] fp32
    const int*   wp     = (const int*)d_in[1];     // [11008,2048] int32 (bytes)
    const float* scales = (const float*)d_in[2];   // [11008,32] fp32
    float* out = (float*)d_out;                    // [4,2048,11008] fp32

    // prep: x -> fp16, W -> dequant fp16
    xcvt_kernel<<<(M_TOT * IN_F / 4) / 256, 256>>>((const float4*)x);
    dequant_kernel<<<(OUT_F * (IN_F / 2) / 4) / 256, 256>>>((const int4*)wp, scales);

    // tensormaps (driver entry point via runtime — no -lcuda link dependency)
    PFN_encodeTiled_local encode = nullptr;
    cudaDriverEntryPointQueryResult qres;
    cudaGetDriverEntryPoint("cuTensorMapEncodeTiled", (void**)&encode,
                            cudaEnableDefault, &qres);
    void *pX = nullptr, *pW = nullptr;
    cudaGetSymbolAddress(&pX, g_X16);
    cudaGetSymbolAddress(&pW, g_W16);

    CUtensorMap tmA, tmB;
    if (encode) {
        cuuint64_t dimsA[2] = {IN_F, M_TOT};
        cuuint64_t strA[1]  = {IN_F * 2};
        cuuint32_t boxA[2]  = {BK, BM};            // 64 halves (=128B, SW128) x 256 rows
        cuuint32_t es[2]    = {1, 1};
        encode(&tmA, CU_TENSOR_MAP_DATA_TYPE_FLOAT16, 2, pX, dimsA, strA, boxA, es,
               CU_TENSOR_MAP_INTERLEAVE_NONE, CU_TENSOR_MAP_SWIZZLE_128B,
               CU_TENSOR_MAP_L2_PROMOTION_L2_128B, CU_TENSOR_MAP_FLOAT_OOB_FILL_NONE);
        cuuint64_t dimsB[2] = {IN_F, OUT_F};
        cuuint64_t strB[1]  = {IN_F * 2};
        cuuint32_t boxB[2]  = {BK, BN};            // 64 halves x 256 rows
        encode(&tmB, CU_TENSOR_MAP_DATA_TYPE_FLOAT16, 2, pW, dimsB, strB, boxB, es,
               CU_TENSOR_MAP_INTERLEAVE_NONE, CU_TENSOR_MAP_SWIZZLE_128B,
               CU_TENSOR_MAP_L2_PROMOTION_L2_128B, CU_TENSOR_MAP_FLOAT_OOB_FILL_NONE);
    }

    cudaFuncSetAttribute(gemm_tc_kernel, cudaFuncAttributeMaxDynamicSharedMemorySize,
                         SMEM_TOTAL);
    dim3 grid(M_TOT / BM, OUT_F / BN);   // (32, 43); m fastest -> B strip L2 reuse
    gemm_tc_kernel<<<grid, GEMM_THREADS, SMEM_TOTAL>>>(tmA, tmB, out);
}

// round 11
// speedup vs baseline: 1.3970x; 1.0202x over previous
#include <cuda_runtime.h>
#include <cuda.h>
#include <cuda_fp16.h>
#include <cstdint>

// Problem constants
#define OUT_F   11008
#define IN_F    4096
#define NGROUPS 32
#define M_TOT   8192        // 4 * 2048

// ---------------------------------------------------------------------------
// tcgen05 is arch-specific; guard so the plain compute_103/sm_103 pass
// compiles empty bodies (the sm_103a image is what executes, proven R7).
// ---------------------------------------------------------------------------
#if defined(__CUDA_ARCH__) && (defined(__CUDA_ARCH_FEAT_SM103_ALL) || \
                               defined(__CUDA_ARCH_FEAT_SM100_ALL) || \
                               defined(__CUDA_ARCH_SPECIFIC__)     || \
                               defined(__CUDA_ARCH_FAMILY_SPECIFIC__))
#define HAS_TCGEN05 1
#else
#define HAS_TCGEN05 0
#endif

// Scratch (device globals — allocation-free per harness rules)
__device__ __align__(16) __half g_W16[(size_t)OUT_F * IN_F];   // ~90 MB
__device__ __align__(16) __half g_X16[(size_t)M_TOT * IN_F];   // ~67 MB

// ---------------------------------------------------------------------------
// x fp32 -> fp16
// ---------------------------------------------------------------------------
__global__ void __launch_bounds__(256) xcvt_kernel(const float4* __restrict__ x) {
    int idx = blockIdx.x * 256 + threadIdx.x;      // exact: M_TOT*IN_F/4 threads
    float4 v = x[idx];
    __half2 h0 = __floats2half2_rn(v.x, v.y);
    __half2 h1 = __floats2half2_rn(v.z, v.w);
    uint2 u;
    u.x = reinterpret_cast<uint32_t&>(h0);
    u.y = reinterpret_cast<uint32_t&>(h1);
    *reinterpret_cast<uint2*>(&g_X16[(size_t)idx * 4]) = u;
}

// ---------------------------------------------------------------------------
// int4 dequant -> fp16 weights (unfused; DRAM-bound, ~30us)
// ---------------------------------------------------------------------------
__global__ void __launch_bounds__(256) dequant_kernel(const int4* __restrict__ wp,
                                                      const float* __restrict__ scales) {
    int idx = blockIdx.x * 256 + threadIdx.x;      // exact: OUT_F*(IN_F/2)/4 threads
    int4 p = wp[idx];
    int base = idx * 4;                            // packed-byte index
    int o = base >> 11;                            // / (IN_F/2 = 2048)
    int c = base & 2047;                           // packed col; output col i = 2c
    int g = c >> 6;                                // group = c/64 (same for all 8 outputs)
    float s = scales[o * NGROUPS + g];
    __align__(16) __half hs[8];
    int v[4] = {p.x, p.y, p.z, p.w};
#pragma unroll
    for (int j = 0; j < 4; j++) {
        int b = v[j] & 0xFF;
        hs[2 * j]     = __float2half_rn((float)((b & 15) - 8) * s);
        hs[2 * j + 1] = __float2half_rn((float)(((b >> 4) & 15) - 8) * s);
    }
    *reinterpret_cast<uint4*>(&g_W16[(size_t)o * IN_F + 2 * c]) = *reinterpret_cast<uint4*>(hs);
}

// ===========================================================================
// 2-CTA tcgen05 GEMM: pair covers M256 x N256, one MMA dispatch per k16.
// Each CTA holds: A slice (its 128 M-rows) + B slice (its 128 N-rows).
// D: 256 f32 TMEM cols per CTA (its M-half x all 256 N cols).
// ===========================================================================
#define BMC 128             // per-CTA M slice (pair = 256)
#define BN  256             // pair N (128 B rows per CTA)
#define BK  64              // halves per stage (128 B rows -> SW128)
#define NSTAGE 6
#define KTILES (IN_F / BK)  // 64
#define GEMM_THREADS 192    // warps 0-3 epilogue, warp 4 TMA, warp 5 MMA(leader)

// SMEM byte offsets
#define SM_TMEMPTR  0
#define SM_FULL(s)  (16 + (s) * 8)
#define SM_EMPTY(s) (64 + (s) * 8)
#define SM_DONE     112
#define SM_A(s)     (1024 + (s) * 16384)           // 6 x 16 KB (A slice / stage)
#define SM_B(s)     (99328 + (s) * 16384)          // 6 x 16 KB (B slice / stage)
#define SMEM_TOTAL  197632
#define STAGE_BYTES 65536                           // pair total per stage (4 x 16 KB)

// idesc: kind::f16, A/B fp16(0), D f32, M=256 (16<<24), N=256 (32<<17)
#define IDESC 0x10400010u

#if HAS_TCGEN05
// SW128 K-major SMEM descriptor base: layout=SW128(2), version=1, SBO=64, LBO=1
#define DESC_BASE ((2ull << 61) | (1ull << 46) | (64ull << 32) | (1ull << 16))
__device__ __forceinline__ uint64_t make_desc(uint32_t addr) {
    return DESC_BASE | ((uint64_t)(addr >> 4) & 0x3FFFull);
}
__device__ __forceinline__ void mbar_init(uint32_t a, uint32_t cnt) {
    asm volatile("mbarrier.init.shared::cta.b64 [%0], %1;" :: "r"(a), "r"(cnt) : "memory");
}
__device__ __forceinline__ void mbar_expect_tx(uint32_t a, uint32_t bytes) {
    asm volatile("mbarrier.arrive.expect_tx.shared::cta.b64 _, [%0], %1;"
                 :: "r"(a), "r"(bytes) : "memory");
}
__device__ __forceinline__ void mbar_wait(uint32_t a, uint32_t parity) {
    asm volatile(
        "{\n\t.reg .pred P;\n\t"
        "W_%=:\n\t"
        "mbarrier.try_wait.parity.shared::cta.b64 P, [%0], %1, 0x989680;\n\t"
        "@P bra.uni D_%=;\n\t"
        "bra.uni W_%=;\n\t"
        "D_%=:\n\t}"
        :: "r"(a), "r"(parity) : "memory");
}
// cg2 TMA: data -> local SMEM, complete_tx -> LEADER's barrier (bit 24 cleared)
__device__ __forceinline__ void tma_2d_cg2(uint32_t dst, const CUtensorMap* m,
                                           int x, int y, uint32_t mbar) {
    asm volatile(
        "{\n\t.reg .b32 lb;\n\t"
        "and.b32 lb, %4, 0xFEFFFFFF;\n\t"
        "cp.async.bulk.tensor.2d.cta_group::2.shared::cluster.global.tile"
        ".mbarrier::complete_tx::bytes [%0], [%1, {%2, %3}], [lb];\n\t}"
        :: "r"(dst), "l"(m), "r"(x), "r"(y), "r"(mbar) : "memory");
}
__device__ __forceinline__ void mma_f16_ss_cg2(uint32_t d, uint64_t ad, uint64_t bd,
                                               uint32_t en) {
    asm volatile(
        "{\n\t.reg .pred p;\n\t"
        "setp.ne.u32 p, %4, 0;\n\t"
        "tcgen05.mma.cta_group::2.kind::f16 [%0], %1, %2, %3, "
        "{%5, %5, %5, %5, %5, %5, %5, %5}, p;\n\t}"
        :: "r"(d), "l"(ad), "l"(bd), "r"(IDESC), "r"(en), "r"(0u) : "memory");
}
__device__ __forceinline__ void tc_commit_mc(uint32_t mbar) {
    asm volatile(
        "tcgen05.commit.cta_group::2.mbarrier::arrive::one.shared::cluster"
        ".multicast::cluster.b64 [%0], %1;"
        :: "r"(mbar), "h"((uint16_t)0x3) : "memory");
}
#endif  // HAS_TCGEN05

__global__ void __launch_bounds__(GEMM_THREADS) __cluster_dims__(2, 1, 1)
gemm_tc_kernel(const __grid_constant__ CUtensorMap tmA,
               const __grid_constant__ CUtensorMap tmB,
               float* __restrict__ out) {
#if HAS_TCGEN05
    extern __shared__ __align__(1024) char smem[];
    uint32_t sbase = (uint32_t)__cvta_generic_to_shared(smem);
    const int tid = threadIdx.x;
    const int wid = tid >> 5;
    const int lane = tid & 31;
    uint32_t rank;
    asm("mov.u32 %0, %%cluster_ctarank;" : "=r"(rank));
    const int m0 = blockIdx.x * BMC;               // rank == blockIdx.x & 1
    const int n0 = blockIdx.y * BN;

    if (wid == 5) {  // collective cg2 TMEM alloc: 256 f32 cols per CTA
        asm volatile("tcgen05.alloc.cta_group::2.sync.aligned.shared::cta.b32 [%0], %1;"
                     :: "r"(sbase + SM_TMEMPTR), "r"(256u) : "memory");
        asm volatile("tcgen05.relinquish_alloc_permit.cta_group::2.sync.aligned;");
    }
    __syncthreads();
    uint32_t tmem;
    asm volatile("ld.shared.b32 %0, [%1];" : "=r"(tmem) : "r"(sbase + SM_TMEMPTR));

    if (tid == 0) {
#pragma unroll
        for (int s = 0; s < NSTAGE; s++) {
            mbar_init(sbase + SM_FULL(s), 1);      // leader: 1 expect-arrive + 4x tx
            mbar_init(sbase + SM_EMPTY(s), 1);     // multicast commit arrive-one
        }
        mbar_init(sbase + SM_DONE, 1);
    }
    __syncthreads();
    // all mbarriers (esp. leader's FULL) must be visible before peer TMA targets them
    asm volatile("barrier.cluster.arrive.aligned;" ::: "memory");
    asm volatile("barrier.cluster.wait.aligned;" ::: "memory");

    if (wid == 4 && lane == 0) {
        // ---- TMA producer (both CTAs): local A slice + local B slice ----
        int phase = 1, s = 0;  // parity 1: first empty-waits pass immediately
        for (int kt = 0; kt < KTILES; kt++) {
            mbar_wait(sbase + SM_EMPTY(s), (uint32_t)phase);
            if (rank == 0)
                mbar_expect_tx(sbase + SM_FULL(s), STAGE_BYTES);
            tma_2d_cg2(sbase + SM_A(s), &tmA, kt * BK, m0, sbase + SM_FULL(s));
            tma_2d_cg2(sbase + SM_B(s), &tmB, kt * BK, n0 + (int)rank * 128,
                       sbase + SM_FULL(s));
            if (++s == NSTAGE) { s = 0; phase ^= 1; }
        }
    } else if (wid == 5 && lane == 0 && rank == 0) {
        // ---- MMA issuer (leader only): 1 x (M256,N256) dispatch per k16 ----
        int phase = 0, s = 0;
        for (int kt = 0; kt < KTILES; kt++) {
            mbar_wait(sbase + SM_FULL(s), (uint32_t)phase);
            uint64_t ad = make_desc(sbase + SM_A(s));  // per-CTA local halves
            uint64_t bd = make_desc(sbase + SM_B(s));
#pragma unroll
            for (int ks = 0; ks < 4; ks++) {       // 4 x k16 per BK=64 stage
                uint32_t en = (kt | ks) ? 1u : 0u;
                mma_f16_ss_cg2(tmem, ad + 2 * ks, bd + 2 * ks, en);
            }
            tc_commit_mc(sbase + SM_EMPTY(s));     // releases BOTH CTAs' stage
            if (++s == NSTAGE) { s = 0; phase ^= 1; }
        }
        tc_commit_mc(sbase + SM_DONE);             // fires in both CTAs when done
    } else if (wid < 4) {
        // ---- epilogue: each CTA reads its M-half (own TMEM), 256 cols ----
        mbar_wait(sbase + SM_DONE, 0);
        asm volatile("tcgen05.fence::after_thread_sync;" ::: "memory");
        int row = m0 + wid * 32 + lane;
        float* orow = out + (size_t)row * OUT_F + n0;
#pragma unroll
        for (int ch = 0; ch < 8; ch++) {           // 8 x 32 cols = 256
            uint32_t r[32];
            asm volatile(
                "tcgen05.ld.sync.aligned.32x32b.x32.b32 "
                "{%0, %1, %2, %3, %4, %5, %6, %7, "
                " %8, %9, %10, %11, %12, %13, %14, %15, "
                " %16, %17, %18, %19, %20, %21, %22, %23, "
                " %24, %25, %26, %27, %28, %29, %30, %31}, [%32];"
                : "=r"(r[0]),  "=r"(r[1]),  "=r"(r[2]),  "=r"(r[3]),
                  "=r"(r[4]),  "=r"(r[5]),  "=r"(r[6]),  "=r"(r[7]),
                  "=r"(r[8]),  "=r"(r[9]),  "=r"(r[10]), "=r"(r[11]),
                  "=r"(r[12]), "=r"(r[13]), "=r"(r[14]), "=r"(r[15]),
                  "=r"(r[16]), "=r"(r[17]), "=r"(r[18]), "=r"(r[19]),
                  "=r"(r[20]), "=r"(r[21]), "=r"(r[22]), "=r"(r[23]),
                  "=r"(r[24]), "=r"(r[25]), "=r"(r[26]), "=r"(r[27]),
                  "=r"(r[28]), "=r"(r[29]), "=r"(r[30]), "=r"(r[31])
                : "r"(tmem + ch * 32));
            asm volatile("tcgen05.wait::ld.sync.aligned;" ::: "memory");
#pragma unroll
            for (int j = 0; j < 8; j++) {
                float4 v = make_float4(__uint_as_float(r[4 * j]),
                                       __uint_as_float(r[4 * j + 1]),
                                       __uint_as_float(r[4 * j + 2]),
                                       __uint_as_float(r[4 * j + 3]));
                *reinterpret_cast<float4*>(orow + ch * 32 + 4 * j) = v;
            }
        }
        asm volatile("tcgen05.fence::before_thread_sync;" ::: "memory");
    }

    __syncthreads();
    if (wid == 5) {  // collective cg2 dealloc
        asm volatile("tcgen05.dealloc.cta_group::2.sync.aligned.b32 %0, %1;"
                     :: "r"(tmem), "r"(256u));
    }
    // no CTA may exit while its pair's MMA/TMA could still touch peer state
    asm volatile("barrier.cluster.arrive.aligned;" ::: "memory");
    asm volatile("barrier.cluster.wait.aligned;" ::: "memory");
#endif  // HAS_TCGEN05
}

// ---------------------------------------------------------------------------
// Launch
// ---------------------------------------------------------------------------
typedef CUresult (CUDAAPI *PFN_encodeTiled_local)(
    CUtensorMap*, CUtensorMapDataType, cuuint32_t, void*,
    const cuuint64_t*, const cuuint64_t*, const cuuint32_t*, const cuuint32_t*,
    CUtensorMapInterleave, CUtensorMapSwizzle, CUtensorMapL2promotion,
    CUtensorMapFloatOOBfill);

extern "C" void kernel_launch(void* const* d_in, const int* in_sizes, int n_in,
                              void* d_out, int out_size) {
    const float* x      = (const float*)d_in[0];   // [4,2048,4096] fp32
    const int*   wp     = (const int*)d_in[1];     // [11008,2048] int32 (bytes)
    const float* scales = (const float*)d_in[2];   // [11008,32] fp32
    float* out = (float*)d_out;                    // [4,2048,11008] fp32

    // prep: x -> fp16, W -> dequant fp16
    xcvt_kernel<<<(M_TOT * IN_F / 4) / 256, 256>>>((const float4*)x);
    dequant_kernel<<<(OUT_F * (IN_F / 2) / 4) / 256, 256>>>((const int4*)wp, scales);

    // tensormaps (driver entry point via runtime — no -lcuda link dependency)
    PFN_encodeTiled_local encode = nullptr;
    cudaDriverEntryPointQueryResult qres;
    cudaGetDriverEntryPoint("cuTensorMapEncodeTiled", (void**)&encode,
                            cudaEnableDefault, &qres);
    void *pX = nullptr, *pW = nullptr;
    cudaGetSymbolAddress(&pX, g_X16);
    cudaGetSymbolAddress(&pW, g_W16);

    CUtensorMap tmA, tmB;
    if (encode) {
        cuuint64_t dimsA[2] = {IN_F, M_TOT};
        cuuint64_t strA[1]  = {IN_F * 2};
        cuuint32_t boxA[2]  = {BK, BMC};           // 64 halves (=128B, SW128) x 128 rows
        cuuint32_t es[2]    = {1, 1};
        encode(&tmA, CU_TENSOR_MAP_DATA_TYPE_FLOAT16, 2, pX, dimsA, strA, boxA, es,
               CU_TENSOR_MAP_INTERLEAVE_NONE, CU_TENSOR_MAP_SWIZZLE_128B,
               CU_TENSOR_MAP_L2_PROMOTION_L2_128B, CU_TENSOR_MAP_FLOAT_OOB_FILL_NONE);
        cuuint64_t dimsB[2] = {IN_F, OUT_F};
        cuuint64_t strB[1]  = {IN_F * 2};
        cuuint32_t boxB[2]  = {BK, 128};           // 64 halves x 128 rows (N/2 per CTA)
        encode(&tmB, CU_TENSOR_MAP_DATA_TYPE_FLOAT16, 2, pW, dimsB, strB, boxB, es,
               CU_TENSOR_MAP_INTERLEAVE_NONE, CU_TENSOR_MAP_SWIZZLE_128B,
               CU_TENSOR_MAP_L2_PROMOTION_L2_128B, CU_TENSOR_MAP_FLOAT_OOB_FILL_NONE);
    }

    cudaFuncSetAttribute(gemm_tc_kernel, cudaFuncAttributeMaxDynamicSharedMemorySize,
                         SMEM_TOTAL);
    dim3 grid(M_TOT / BMC, OUT_F / BN);  // (64, 43); adjacent x-CTAs form a cluster
    gemm_tc_kernel<<<grid, GEMM_THREADS, SMEM_TOTAL>>>(tmA, tmB, out);
}

// round 12
// speedup vs baseline: 1.4408x; 1.0314x over previous
#include <cuda_runtime.h>
#include <cuda.h>
#include <cuda_fp16.h>
#include <cstdint>

// Problem constants
#define OUT_F   11008
#define IN_F    4096
#define NGROUPS 32
#define M_TOT   8192        // 4 * 2048

#if defined(__CUDA_ARCH__) && (defined(__CUDA_ARCH_FEAT_SM103_ALL) || \
                               defined(__CUDA_ARCH_FEAT_SM100_ALL) || \
                               defined(__CUDA_ARCH_SPECIFIC__)     || \
                               defined(__CUDA_ARCH_FAMILY_SPECIFIC__))
#define HAS_TCGEN05 1
#else
#define HAS_TCGEN05 0
#endif

// Scratch (device globals — allocation-free per harness rules)
__device__ __align__(16) __half g_W16[(size_t)OUT_F * IN_F];   // ~90 MB
__device__ __align__(16) __half g_X16[(size_t)M_TOT * IN_F];   // ~67 MB

// ---------------------------------------------------------------------------
// x fp32 -> fp16
// ---------------------------------------------------------------------------
__global__ void __launch_bounds__(256) xcvt_kernel(const float4* __restrict__ x) {
    int idx = blockIdx.x * 256 + threadIdx.x;      // exact: M_TOT*IN_F/4 threads
    float4 v = x[idx];
    __half2 h0 = __floats2half2_rn(v.x, v.y);
    __half2 h1 = __floats2half2_rn(v.z, v.w);
    uint2 u;
    u.x = reinterpret_cast<uint32_t&>(h0);
    u.y = reinterpret_cast<uint32_t&>(h1);
    *reinterpret_cast<uint2*>(&g_X16[(size_t)idx * 4]) = u;
}

// ---------------------------------------------------------------------------
// int4 dequant -> fp16 weights (unfused; DRAM-bound, ~30us)
// ---------------------------------------------------------------------------
__global__ void __launch_bounds__(256) dequant_kernel(const int4* __restrict__ wp,
                                                      const float* __restrict__ scales) {
    int idx = blockIdx.x * 256 + threadIdx.x;      // exact: OUT_F*(IN_F/2)/4 threads
    int4 p = wp[idx];
    int base = idx * 4;                            // packed-byte index
    int o = base >> 11;                            // / (IN_F/2 = 2048)
    int c = base & 2047;                           // packed col; output col i = 2c
    int g = c >> 6;                                // group = c/64 (same for all 8 outputs)
    float s = scales[o * NGROUPS + g];
    __align__(16) __half hs[8];
    int v[4] = {p.x, p.y, p.z, p.w};
#pragma unroll
    for (int j = 0; j < 4; j++) {
        int b = v[j] & 0xFF;
        hs[2 * j]     = __float2half_rn((float)((b & 15) - 8) * s);
        hs[2 * j + 1] = __float2half_rn((float)(((b >> 4) & 15) - 8) * s);
    }
    *reinterpret_cast<uint4*>(&g_W16[(size_t)o * IN_F + 2 * c]) = *reinterpret_cast<uint4*>(hs);
}

// ===========================================================================
// Persistent 2-CTA tcgen05 GEMM with double-buffered TMEM accumulators.
// 74 cg2 pairs loop over 1376 M256xN256 tiles; MMA fills buf(i&1) while
// epilogue drains buf((i-1)&1). TMA ring runs continuously across tiles.
// ===========================================================================
#define BMC 128             // per-CTA M slice (pair = 256)
#define BN  256             // pair N (128 B rows per CTA)
#define BK  64              // halves per stage (128 B rows -> SW128)
#define NSTAGE 6
#define KTILES (IN_F / BK)  // 64 stages per tile
#define NTILES ((M_TOT / 256) * (OUT_F / BN))   // 32*43 = 1376 pair-tiles
#define NPAIRS 74
#define MTILES (M_TOT / 256)                    // 32 (m fastest -> B strip reuse)
#define GEMM_THREADS 192    // warps 0-3 epilogue, warp 4 TMA, warp 5 MMA(leader)

// SMEM byte offsets
#define SM_TMEMPTR  0
#define SM_FULL(s)  (16 + (s) * 8)
#define SM_EMPTY(s) (64 + (s) * 8)
#define SM_ACCD(b)  (112 + (b) * 8)    // accumulator-ready (multicast commit)
#define SM_EPIF(b)  (128 + (b) * 8)    // accumulator-free (leader's, count=2)
#define SM_A(s)     (1024 + (s) * 16384)           // 6 x 16 KB (A slice / stage)
#define SM_B(s)     (99328 + (s) * 16384)          // 6 x 16 KB (B slice / stage)
#define SMEM_TOTAL  197632
#define STAGE_BYTES 65536                           // pair total per stage

// idesc: kind::f16, A/B fp16(0), D f32, M=256 (16<<24), N=256 (32<<17)
#define IDESC 0x10400010u

#if HAS_TCGEN05
// SW128 K-major SMEM descriptor base: layout=SW128(2), version=1, SBO=64, LBO=1
#define DESC_BASE ((2ull << 61) | (1ull << 46) | (64ull << 32) | (1ull << 16))
__device__ __forceinline__ uint64_t make_desc(uint32_t addr) {
    return DESC_BASE | ((uint64_t)(addr >> 4) & 0x3FFFull);
}
__device__ __forceinline__ void mbar_init(uint32_t a, uint32_t cnt) {
    asm volatile("mbarrier.init.shared::cta.b64 [%0], %1;" :: "r"(a), "r"(cnt) : "memory");
}
__device__ __forceinline__ void mbar_expect_tx(uint32_t a, uint32_t bytes) {
    asm volatile("mbarrier.arrive.expect_tx.shared::cta.b64 _, [%0], %1;"
                 :: "r"(a), "r"(bytes) : "memory");
}
__device__ __forceinline__ void mbar_wait(uint32_t a, uint32_t parity) {
    asm volatile(
        "{\n\t.reg .pred P;\n\t"
        "W_%=:\n\t"
        "mbarrier.try_wait.parity.shared::cta.b64 P, [%0], %1, 0x989680;\n\t"
        "@P bra.uni D_%=;\n\t"
        "bra.uni W_%=;\n\t"
        "D_%=:\n\t}"
        :: "r"(a), "r"(parity) : "memory");
}
// arrive on CLUSTER RANK 0's barrier at the same SMEM offset
__device__ __forceinline__ void mbar_arrive_rank0(uint32_t a) {
    asm volatile(
        "{\n\t.reg .b32 ra;\n\t"
        "mapa.shared::cluster.u32 ra, %0, 0;\n\t"
        "mbarrier.arrive.shared::cluster.b64 _, [ra];\n\t}"
        :: "r"(a) : "memory");
}
// cg2 TMA: data -> local SMEM, complete_tx -> LEADER's barrier (bit 24 cleared)
__device__ __forceinline__ void tma_2d_cg2(uint32_t dst, const CUtensorMap* m,
                                           int x, int y, uint32_t mbar) {
    asm volatile(
        "{\n\t.reg .b32 lb;\n\t"
        "and.b32 lb, %4, 0xFEFFFFFF;\n\t"
        "cp.async.bulk.tensor.2d.cta_group::2.shared::cluster.global.tile"
        ".mbarrier::complete_tx::bytes [%0], [%1, {%2, %3}], [lb];\n\t}"
        :: "r"(dst), "l"(m), "r"(x), "r"(y), "r"(mbar) : "memory");
}
__device__ __forceinline__ void mma_f16_ss_cg2(uint32_t d, uint64_t ad, uint64_t bd,
                                               uint32_t en) {
    asm volatile(
        "{\n\t.reg .pred p;\n\t"
        "setp.ne.u32 p, %4, 0;\n\t"
        "tcgen05.mma.cta_group::2.kind::f16 [%0], %1, %2, %3, "
        "{%5, %5, %5, %5, %5, %5, %5, %5}, p;\n\t}"
        :: "r"(d), "l"(ad), "l"(bd), "r"(IDESC), "r"(en), "r"(0u) : "memory");
}
__device__ __forceinline__ void tc_commit_mc(uint32_t mbar) {
    asm volatile(
        "tcgen05.commit.cta_group::2.mbarrier::arrive::one.shared::cluster"
        ".multicast::cluster.b64 [%0], %1;"
        :: "r"(mbar), "h"((uint16_t)0x3) : "memory");
}
#endif  // HAS_TCGEN05

__global__ void __launch_bounds__(GEMM_THREADS) __cluster_dims__(2, 1, 1)
gemm_tc_kernel(const __grid_constant__ CUtensorMap tmA,
               const __grid_constant__ CUtensorMap tmB,
               float* __restrict__ out) {
#if HAS_TCGEN05
    extern __shared__ __align__(1024) char smem[];
    uint32_t sbase = (uint32_t)__cvta_generic_to_shared(smem);
    const int tid = threadIdx.x;
    const int wid = tid >> 5;
    const int lane = tid & 31;
    uint32_t rank;
    asm("mov.u32 %0, %%cluster_ctarank;" : "=r"(rank));
    const int pair = blockIdx.x >> 1;              // 0..73

    if (wid == 5) {  // collective cg2 TMEM alloc: 512 f32 cols (2 x 256 bufs)
        asm volatile("tcgen05.alloc.cta_group::2.sync.aligned.shared::cta.b32 [%0], %1;"
                     :: "r"(sbase + SM_TMEMPTR), "r"(512u) : "memory");
        asm volatile("tcgen05.relinquish_alloc_permit.cta_group::2.sync.aligned;");
    }
    __syncthreads();
    uint32_t tmem;
    asm volatile("ld.shared.b32 %0, [%1];" : "=r"(tmem) : "r"(sbase + SM_TMEMPTR));

    if (tid == 0) {
#pragma unroll
        for (int s = 0; s < NSTAGE; s++) {
            mbar_init(sbase + SM_FULL(s), 1);      // leader: 1 expect-arrive + 4x tx
            mbar_init(sbase + SM_EMPTY(s), 1);     // multicast commit arrive-one
        }
        mbar_init(sbase + SM_ACCD(0), 1);          // multicast commit arrive-one
        mbar_init(sbase + SM_ACCD(1), 1);
        mbar_init(sbase + SM_EPIF(0), 2);          // one arrive per CTA's epilogue
        mbar_init(sbase + SM_EPIF(1), 2);
    }
    __syncthreads();
    // all mbarriers visible cluster-wide before peer TMA / mapa-arrives target them
    asm volatile("barrier.cluster.arrive.aligned;" ::: "memory");
    asm volatile("barrier.cluster.wait.aligned;" ::: "memory");

    if (wid == 4 && lane == 0) {
        // ---- TMA producer (both CTAs): continuous ring across all tiles ----
        int phase = 1, s = 0;  // parity 1: first empty-waits pass immediately
        for (int t = pair; t < NTILES; t += NPAIRS) {
            const int m0 = (t % MTILES) * 256 + (int)rank * BMC;
            const int nb = (t / MTILES) * BN + (int)rank * 128;   // B slice rows
            for (int kt = 0; kt < KTILES; kt++) {
                mbar_wait(sbase + SM_EMPTY(s), (uint32_t)phase);
                if (rank == 0)
                    mbar_expect_tx(sbase + SM_FULL(s), STAGE_BYTES);
                tma_2d_cg2(sbase + SM_A(s), &tmA, kt * BK, m0, sbase + SM_FULL(s));
                tma_2d_cg2(sbase + SM_B(s), &tmB, kt * BK, nb, sbase + SM_FULL(s));
                if (++s == NSTAGE) { s = 0; phase ^= 1; }
            }
        }
    } else if (wid == 5 && lane == 0 && rank == 0) {
        // ---- MMA issuer (leader only): fill buf(i&1), one dispatch per k16 ----
        int phase = 0, s = 0, i = 0;
        for (int t = pair; t < NTILES; t += NPAIRS, i++) {
            const int b = i & 1, j = i >> 1;
            mbar_wait(sbase + SM_EPIF(b), (uint32_t)((j & 1) ^ 1));  // buf drained
            const uint32_t d = tmem + (uint32_t)b * 256;
            for (int kt = 0; kt < KTILES; kt++) {
                mbar_wait(sbase + SM_FULL(s), (uint32_t)phase);
                uint64_t ad = make_desc(sbase + SM_A(s));
                uint64_t bd = make_desc(sbase + SM_B(s));
#pragma unroll
                for (int ks = 0; ks < 4; ks++) {
                    uint32_t en = (kt | ks) ? 1u : 0u;   // reset acc per tile
                    mma_f16_ss_cg2(d, ad + 2 * ks, bd + 2 * ks, en);
                }
                tc_commit_mc(sbase + SM_EMPTY(s));       // releases stage both CTAs
                if (++s == NSTAGE) { s = 0; phase ^= 1; }
            }
            tc_commit_mc(sbase + SM_ACCD(b));            // buf ready, both CTAs
        }
    } else if (wid < 4) {
        // ---- epilogue (both CTAs): drain buf of tile i while tile i+1 runs ----
        int i = 0;
        for (int t = pair; t < NTILES; t += NPAIRS, i++) {
            const int b = i & 1, j = i >> 1;
            mbar_wait(sbase + SM_ACCD(b), (uint32_t)(j & 1));
            asm volatile("tcgen05.fence::after_thread_sync;" ::: "memory");
            const int m0 = (t % MTILES) * 256 + (int)rank * BMC;
            const int n0 = (t / MTILES) * BN;
            int row = m0 + wid * 32 + lane;
            float* orow = out + (size_t)row * OUT_F + n0;
            const uint32_t dbase = tmem + (uint32_t)b * 256;
#pragma unroll
            for (int ch = 0; ch < 8; ch++) {             // 8 x 32 cols = 256
                uint32_t r[32];
                asm volatile(
                    "tcgen05.ld.sync.aligned.32x32b.x32.b32 "
                    "{%0, %1, %2, %3, %4, %5, %6, %7, "
                    " %8, %9, %10, %11, %12, %13, %14, %15, "
                    " %16, %17, %18, %19, %20, %21, %22, %23, "
                    " %24, %25, %26, %27, %28, %29, %30, %31}, [%32];"
                    : "=r"(r[0]),  "=r"(r[1]),  "=r"(r[2]),  "=r"(r[3]),
                      "=r"(r[4]),  "=r"(r[5]),  "=r"(r[6]),  "=r"(r[7]),
                      "=r"(r[8]),  "=r"(r[9]),  "=r"(r[10]), "=r"(r[11]),
                      "=r"(r[12]), "=r"(r[13]), "=r"(r[14]), "=r"(r[15]),
                      "=r"(r[16]), "=r"(r[17]), "=r"(r[18]), "=r"(r[19]),
                      "=r"(r[20]), "=r"(r[21]), "=r"(r[22]), "=r"(r[23]),
                      "=r"(r[24]), "=r"(r[25]), "=r"(r[26]), "=r"(r[27]),
                      "=r"(r[28]), "=r"(r[29]), "=r"(r[30]), "=r"(r[31])
                    : "r"(dbase + ch * 32));
                asm volatile("tcgen05.wait::ld.sync.aligned;" ::: "memory");
#pragma unroll
                for (int jj = 0; jj < 8; jj++) {
                    float4 v = make_float4(__uint_as_float(r[4 * jj]),
                                           __uint_as_float(r[4 * jj + 1]),
                                           __uint_as_float(r[4 * jj + 2]),
                                           __uint_as_float(r[4 * jj + 3]));
                    *reinterpret_cast<float4*>(orow + ch * 32 + 4 * jj) = v;
                }
            }
            asm volatile("tcgen05.fence::before_thread_sync;" ::: "memory");
            // all 4 epilogue warps of this CTA done with buf -> one arrive to leader
            asm volatile("bar.sync 1, 128;" ::: "memory");
            if (tid == 0) mbar_arrive_rank0(sbase + SM_EPIF(b));
        }
    }

    __syncthreads();
    asm volatile("barrier.cluster.arrive.aligned;" ::: "memory");
    asm volatile("barrier.cluster.wait.aligned;" ::: "memory");
    if (wid == 5) {  // collective cg2 dealloc
        asm volatile("tcgen05.dealloc.cta_group::2.sync.aligned.b32 %0, %1;"
                     :: "r"(tmem), "r"(512u));
    }
    asm volatile("barrier.cluster.arrive.aligned;" ::: "memory");
    asm volatile("barrier.cluster.wait.aligned;" ::: "memory");
#endif  // HAS_TCGEN05
}

// ---------------------------------------------------------------------------
// Launch
// ---------------------------------------------------------------------------
typedef CUresult (CUDAAPI *PFN_encodeTiled_local)(
    CUtensorMap*, CUtensorMapDataType, cuuint32_t, void*,
    const cuuint64_t*, const cuuint64_t*, const cuuint32_t*, const cuuint32_t*,
    CUtensorMapInterleave, CUtensorMapSwizzle, CUtensorMapL2promotion,
    CUtensorMapFloatOOBfill);

extern "C" void kernel_launch(void* const* d_in, const int* in_sizes, int n_in,
                              void* d_out, int out_size) {
    const float* x      = (const float*)d_in[0];   // [4,2048,4096] fp32
    const int*   wp     = (const int*)d_in[1];     // [11008,2048] int32 (bytes)
    const float* scales = (const float*)d_in[2];   // [11008,32] fp32
    float* out = (float*)d_out;                    // [4,2048,11008] fp32

    // prep: x -> fp16, W -> dequant fp16
    xcvt_kernel<<<(M_TOT * IN_F / 4) / 256, 256>>>((const float4*)x);
    dequant_kernel<<<(OUT_F * (IN_F / 2) / 4) / 256, 256>>>((const int4*)wp, scales);

    // tensormaps (driver entry point via runtime — no -lcuda link dependency)
    PFN_encodeTiled_local encode = nullptr;
    cudaDriverEntryPointQueryResult qres;
    cudaGetDriverEntryPoint("cuTensorMapEncodeTiled", (void**)&encode,
                            cudaEnableDefault, &qres);
    void *pX = nullptr, *pW = nullptr;
    cudaGetSymbolAddress(&pX, g_X16);
    cudaGetSymbolAddress(&pW, g_W16);

    CUtensorMap tmA, tmB;
    if (encode) {
        cuuint64_t dimsA[2] = {IN_F, M_TOT};
        cuuint64_t strA[1]  = {IN_F * 2};
        cuuint32_t boxA[2]  = {BK, BMC};           // 64 halves (=128B, SW128) x 128 rows
        cuuint32_t es[2]    = {1, 1};
        encode(&tmA, CU_TENSOR_MAP_DATA_TYPE_FLOAT16, 2, pX, dimsA, strA, boxA, es,
               CU_TENSOR_MAP_INTERLEAVE_NONE, CU_TENSOR_MAP_SWIZZLE_128B,
               CU_TENSOR_MAP_L2_PROMOTION_L2_128B, CU_TENSOR_MAP_FLOAT_OOB_FILL_NONE);
        cuuint64_t dimsB[2] = {IN_F, OUT_F};
        cuuint64_t strB[1]  = {IN_F * 2};
        cuuint32_t boxB[2]  = {BK, 128};           // 64 halves x 128 rows (N/2 per CTA)
        encode(&tmB, CU_TENSOR_MAP_DATA_TYPE_FLOAT16, 2, pW, dimsB, strB, boxB, es,
               CU_TENSOR_MAP_INTERLEAVE_NONE, CU_TENSOR_MAP_SWIZZLE_128B,
               CU_TENSOR_MAP_L2_PROMOTION_L2_128B, CU_TENSOR_MAP_FLOAT_OOB_FILL_NONE);
    }

    cudaFuncSetAttribute(gemm_tc_kernel, cudaFuncAttributeMaxDynamicSharedMemorySize,
                         SMEM_TOTAL);
    gemm_tc_kernel<<<dim3(2 * NPAIRS, 1), GEMM_THREADS, SMEM_TOTAL>>>(tmA, tmB, out);
}

// round 17
// speedup vs baseline: 1.5398x; 1.0688x over previous
#include <cuda_runtime.h>
#include <cuda.h>
#include <cuda_fp16.h>
#include <cstdint>

// Problem constants
#define OUT_F   11008
#define IN_F    4096
#define NGROUPS 32
#define M_TOT   8192        // 4 * 2048

#if defined(__CUDA_ARCH__) && (defined(__CUDA_ARCH_FEAT_SM103_ALL) || \
                               defined(__CUDA_ARCH_FEAT_SM100_ALL) || \
                               defined(__CUDA_ARCH_SPECIFIC__)     || \
                               defined(__CUDA_ARCH_FAMILY_SPECIFIC__))
#define HAS_TCGEN05 1
#else
#define HAS_TCGEN05 0
#endif

// Scratch (device globals — allocation-free per harness rules)
__device__ __align__(16) __half g_W16[(size_t)OUT_F * IN_F];   // ~90 MB
__device__ __align__(16) __half g_X16[(size_t)M_TOT * IN_F];   // ~67 MB
__device__ unsigned g_ready[64];        // per-n-strip dequant completion (count to 8)
__device__ unsigned g_bar_cnt = 0;      // software grid barrier (self-cleaning)
__device__ volatile unsigned g_bar_gen = 0;

// ===========================================================================
// Persistent 2-CTA tcgen05 GEMM, in-kernel prep + JIT weight dequant.
// ===========================================================================
#define BMC 128             // per-CTA M slice (pair = 256)
#define BN  256             // pair N (128 B rows per CTA)
#define BK  64              // halves per stage (128 B rows -> SW128)
#define NSTAGE 6
#define KTILES (IN_F / BK)  // 64 stages per tile
#define NTILES ((M_TOT / 256) * (OUT_F / BN))   // 32*43 = 1376 pair-tiles
#define NPAIRS 74
#define NCTAS  148
#define MTILES (M_TOT / 256)                    // 32 (m fastest -> B strip reuse)
#define NSTRIPS (OUT_F / BN)                    // 43 W n-strips (256 rows each)
#define PRE_STRIPS 13                           // strips dequanted in phase 0
#define STRIP_I4  131072                        // int4 loads per strip (256*2048/4)
#define GEMM_THREADS 256    // w0-3 epilogue, w4 TMA, w5 MMA, w6-7 dequant crews

// SMEM byte offsets
#define SM_TMEMPTR  0
#define SM_FULL(s)  (16 + (s) * 8)
#define SM_EMPTY(s) (64 + (s) * 8)
#define SM_ACCD(b)  (112 + (b) * 8)    // accumulator-ready (multicast commit)
#define SM_EPIF(b)  (128 + (b) * 8)    // accumulator-free (leader's, count=2)
#define SM_A(s)     (1024 + (s) * 16384)           // 6 x 16 KB
#define SM_B(s)     (99328 + (s) * 16384)          // 6 x 16 KB
#define SMEM_TOTAL  197632
#define STAGE_BYTES 65536                           // pair total per stage

// idesc: kind::f16, A/B fp16(0), D f32, M=256 (16<<24), N=256 (32<<17)
#define IDESC 0x10400010u

#if HAS_TCGEN05
#define DESC_BASE ((2ull << 61) | (1ull << 46) | (64ull << 32) | (1ull << 16))
__device__ __forceinline__ uint64_t make_desc(uint32_t addr) {
    return DESC_BASE | ((uint64_t)(addr >> 4) & 0x3FFFull);
}
__device__ __forceinline__ void mbar_init(uint32_t a, uint32_t cnt) {
    asm volatile("mbarrier.init.shared::cta.b64 [%0], %1;" :: "r"(a), "r"(cnt) : "memory");
}
__device__ __forceinline__ void mbar_expect_tx(uint32_t a, uint32_t bytes) {
    asm volatile("mbarrier.arrive.expect_tx.shared::cta.b64 _, [%0], %1;"
                 :: "r"(a), "r"(bytes) : "memory");
}
__device__ __forceinline__ void mbar_wait(uint32_t a, uint32_t parity) {
    asm volatile(
        "{\n\t.reg .pred P;\n\t"
        "W_%=:\n\t"
        "mbarrier.try_wait.parity.shared::cta.b64 P, [%0], %1, 0x989680;\n\t"
        "@P bra.uni D_%=;\n\t"
        "bra.uni W_%=;\n\t"
        "D_%=:\n\t}"
        :: "r"(a), "r"(parity) : "memory");
}
__device__ __forceinline__ void mbar_arrive_rank0(uint32_t a) {
    asm volatile(
        "{\n\t.reg .b32 ra;\n\t"
        "mapa.shared::cluster.u32 ra, %0, 0;\n\t"
        "mbarrier.arrive.shared::cluster.b64 _, [ra];\n\t}"
        :: "r"(a) : "memory");
}
__device__ __forceinline__ void tma_2d_cg2(uint32_t dst, const CUtensorMap* m,
                                           int x, int y, uint32_t mbar) {
    asm volatile(
        "{\n\t.reg .b32 lb;\n\t"
        "and.b32 lb, %4, 0xFEFFFFFF;\n\t"
        "cp.async.bulk.tensor.2d.cta_group::2.shared::cluster.global.tile"
        ".mbarrier::complete_tx::bytes [%0], [%1, {%2, %3}], [lb];\n\t}"
        :: "r"(dst), "l"(m), "r"(x), "r"(y), "r"(mbar) : "memory");
}
__device__ __forceinline__ void mma_f16_ss_cg2(uint32_t d, uint64_t ad, uint64_t bd,
                                               uint32_t en) {
    asm volatile(
        "{\n\t.reg .pred p;\n\t"
        "setp.ne.u32 p, %4, 0;\n\t"
        "tcgen05.mma.cta_group::2.kind::f16 [%0], %1, %2, %3, "
        "{%5, %5, %5, %5, %5, %5, %5, %5}, p;\n\t}"
        :: "r"(d), "l"(ad), "l"(bd), "r"(IDESC), "r"(en), "r"(0u) : "memory");
}
__device__ __forceinline__ void tc_commit_mc(uint32_t mbar) {
    asm volatile(
        "tcgen05.commit.cta_group::2.mbarrier::arrive::one.shared::cluster"
        ".multicast::cluster.b64 [%0], %1;"
        :: "r"(mbar), "h"((uint16_t)0x3) : "memory");
}

// dequant one int4 (4 packed bytes -> 8 fp16) at global packed-int4 index idx
__device__ __forceinline__ void dq_store_i4(int idx, const int4* __restrict__ wp,
                                            const float* __restrict__ scales) {
    int4 p = wp[idx];
    int base = idx * 4;                 // packed-byte index
    int o = base >> 11;                 // / (IN_F/2 = 2048)
    int c = base & 2047;
    int g = c >> 6;
    float s = scales[o * NGROUPS + g];
    __align__(16) __half hs[8];
    int v[4] = {p.x, p.y, p.z, p.w};
#pragma unroll
    for (int j = 0; j < 4; j++) {
        int b = v[j] & 0xFF;
        hs[2 * j]     = __float2half_rn((float)((b & 15) - 8) * s);
        hs[2 * j + 1] = __float2half_rn((float)(((b >> 4) & 15) - 8) * s);
    }
    *reinterpret_cast<uint4*>(&g_W16[(size_t)o * IN_F + 2 * c]) = *reinterpret_cast<uint4*>(hs);
}

// sense-reversing grid barrier; all NCTAS CTAs resident (persistent launch)
__device__ __forceinline__ void grid_bar_tid0() {
    unsigned my = g_bar_gen;
    __threadfence();
    unsigned old = atomicAdd(&g_bar_cnt, 1);
    if (old == NCTAS - 1) {
        g_bar_cnt = 0;
        __threadfence();
        atomicAdd((unsigned*)&g_bar_gen, 1);
    } else {
        while (g_bar_gen == my) __nanosleep(64);
    }
    __threadfence();
}
#endif  // HAS_TCGEN05

__global__ void __launch_bounds__(GEMM_THREADS) __cluster_dims__(2, 1, 1)
gemm_tc_kernel(const __grid_constant__ CUtensorMap tmA,
               const __grid_constant__ CUtensorMap tmB,
               const float4* __restrict__ x,
               const int4* __restrict__ wp,
               const float* __restrict__ scales,
               float* __restrict__ out) {
#if HAS_TCGEN05
    extern __shared__ __align__(1024) char smem[];
    uint32_t sbase = (uint32_t)__cvta_generic_to_shared(smem);
    const int tid = threadIdx.x;
    const int wid = tid >> 5;
    const int lane = tid & 31;
    uint32_t rank;
    asm("mov.u32 %0, %%cluster_ctarank;" : "=r"(rank));
    const int pair = blockIdx.x >> 1;              // 0..73

    if (wid == 5) {  // collective cg2 TMEM alloc: 512 f32 cols (2 x 256 bufs)
        asm volatile("tcgen05.alloc.cta_group::2.sync.aligned.shared::cta.b32 [%0], %1;"
                     :: "r"(sbase + SM_TMEMPTR), "r"(512u) : "memory");
        asm volatile("tcgen05.relinquish_alloc_permit.cta_group::2.sync.aligned;");
    }
    __syncthreads();
    uint32_t tmem;
    asm volatile("ld.shared.b32 %0, [%1];" : "=r"(tmem) : "r"(sbase + SM_TMEMPTR));

    if (tid == 0) {
#pragma unroll
        for (int s = 0; s < NSTAGE; s++) {
            mbar_init(sbase + SM_FULL(s), 1);
            mbar_init(sbase + SM_EMPTY(s), 1);
        }
        mbar_init(sbase + SM_ACCD(0), 1);
        mbar_init(sbase + SM_ACCD(1), 1);
        mbar_init(sbase + SM_EPIF(0), 2);
        mbar_init(sbase + SM_EPIF(1), 2);
    }
    __syncthreads();
    asm volatile("barrier.cluster.arrive.aligned;" ::: "memory");
    asm volatile("barrier.cluster.wait.aligned;" ::: "memory");

    // ================= Phase 0: prep (all CTAs, all 256 threads) =============
    {
        const int gt = (int)blockIdx.x * GEMM_THREADS + tid;   // 0..37887
        const int gstride = NCTAS * GEMM_THREADS;
        if (tid < NSTRIPS) g_ready[tid] = 0;                   // reset (replays!)
        // x fp32 -> fp16 (full)
        for (int idx = gt; idx < M_TOT * IN_F / 4; idx += gstride) {
            float4 v = x[idx];
            __half2 h0 = __floats2half2_rn(v.x, v.y);
            __half2 h1 = __floats2half2_rn(v.z, v.w);
            uint2 u;
            u.x = reinterpret_cast<uint32_t&>(h0);
            u.y = reinterpret_cast<uint32_t&>(h1);
            *reinterpret_cast<uint2*>(&g_X16[(size_t)idx * 4]) = u;
        }
        // W strips 0..PRE_STRIPS-1
        for (int idx = gt; idx < PRE_STRIPS * STRIP_I4; idx += gstride)
            dq_store_i4(idx, wp, scales);
        __threadfence();
        __syncthreads();
        if (tid == 0) grid_bar_tid0();
        __syncthreads();
    }

    // ================= Mainloop (R12 structure) + JIT dequant crews ==========
    if (wid == 4 && lane == 0) {
        // ---- TMA producer (both CTAs), gated on W strip readiness ----
        int phase = 1, s = 0;
        for (int t = pair; t < NTILES; t += NPAIRS) {
            const int m0 = (t % MTILES) * 256 + (int)rank * BMC;
            const int ns = t / MTILES;
            const int nb = ns * BN + (int)rank * 128;
            if (ns >= PRE_STRIPS) {
                unsigned v;
                do {
                    asm volatile("ld.acquire.gpu.global.u32 %0, [%1];"
                                 : "=r"(v) : "l"(&g_ready[ns]));
                    if (v < 8u) __nanosleep(128);
                } while (v < 8u);
            }
            for (int kt = 0; kt < KTILES; kt++) {
                mbar_wait(sbase + SM_EMPTY(s), (uint32_t)phase);
                if (rank == 0)
                    mbar_expect_tx(sbase + SM_FULL(s), STAGE_BYTES);
                tma_2d_cg2(sbase + SM_A(s), &tmA, kt * BK, m0, sbase + SM_FULL(s));
                tma_2d_cg2(sbase + SM_B(s), &tmB, kt * BK, nb, sbase + SM_FULL(s));
                if (++s == NSTAGE) { s = 0; phase ^= 1; }
            }
        }
    } else if (wid == 5 && lane == 0 && rank == 0) {
        // ---- MMA issuer (leader only): fill buf(i&1) ----
        int phase = 0, s = 0, i = 0;
        for (int t = pair; t < NTILES; t += NPAIRS, i++) {
            const int b = i & 1, j = i >> 1;
            mbar_wait(sbase + SM_EPIF(b), (uint32_t)((j & 1) ^ 1));
            const uint32_t d = tmem + (uint32_t)b * 256;
            for (int kt = 0; kt < KTILES; kt++) {
                mbar_wait(sbase + SM_FULL(s), (uint32_t)phase);
                uint64_t ad = make_desc(sbase + SM_A(s));
                uint64_t bd = make_desc(sbase + SM_B(s));
#pragma unroll
                for (int ks = 0; ks < 4; ks++) {
                    uint32_t en = (kt | ks) ? 1u : 0u;
                    mma_f16_ss_cg2(d, ad + 2 * ks, bd + 2 * ks, en);
                }
                tc_commit_mc(sbase + SM_EMPTY(s));
                if (++s == NSTAGE) { s = 0; phase ^= 1; }
            }
            tc_commit_mc(sbase + SM_ACCD(b));
        }
    } else if (wid < 4) {
        // ---- epilogue (both CTAs): drain buf of tile i while i+1 runs ----
        int i = 0;
        for (int t = pair; t < NTILES; t += NPAIRS, i++) {
            const int b = i & 1, j = i >> 1;
            mbar_wait(sbase + SM_ACCD(b), (uint32_t)(j & 1));
            asm volatile("tcgen05.fence::after_thread_sync;" ::: "memory");
            const int m0 = (t % MTILES) * 256 + (int)rank * BMC;
            const int n0 = (t / MTILES) * BN;
            int row = m0 + wid * 32 + lane;
            float* orow = out + (size_t)row * OUT_F + n0;
            const uint32_t dbase = tmem + (uint32_t)b * 256;
#pragma unroll
            for (int ch = 0; ch < 8; ch++) {
                uint32_t r[32];
                asm volatile(
                    "tcgen05.ld.sync.aligned.32x32b.x32.b32 "
                    "{%0, %1, %2, %3, %4, %5, %6, %7, "
                    " %8, %9, %10, %11, %12, %13, %14, %15, "
                    " %16, %17, %18, %19, %20, %21, %22, %23, "
                    " %24, %25, %26, %27, %28, %29, %30, %31}, [%32];"
                    : "=r"(r[0]),  "=r"(r[1]),  "=r"(r[2]),  "=r"(r[3]),
                      "=r"(r[4]),  "=r"(r[5]),  "=r"(r[6]),  "=r"(r[7]),
                      "=r"(r[8]),  "=r"(r[9]),  "=r"(r[10]), "=r"(r[11]),
                      "=r"(r[12]), "=r"(r[13]), "=r"(r[14]), "=r"(r[15]),
                      "=r"(r[16]), "=r"(r[17]), "=r"(r[18]), "=r"(r[19]),
                      "=r"(r[20]), "=r"(r[21]), "=r"(r[22]), "=r"(r[23]),
                      "=r"(r[24]), "=r"(r[25]), "=r"(r[26]), "=r"(r[27]),
                      "=r"(r[28]), "=r"(r[29]), "=r"(r[30]), "=r"(r[31])
                    : "r"(dbase + ch * 32));
                asm volatile("tcgen05.wait::ld.sync.aligned;" ::: "memory");
#pragma unroll
                for (int jj = 0; jj < 8; jj++) {
                    float4 v = make_float4(__uint_as_float(r[4 * jj]),
                                           __uint_as_float(r[4 * jj + 1]),
                                           __uint_as_float(r[4 * jj + 2]),
                                           __uint_as_float(r[4 * jj + 3]));
                    *reinterpret_cast<float4*>(orow + ch * 32 + 4 * jj) = v;
                }
            }
            asm volatile("tcgen05.fence::before_thread_sync;" ::: "memory");
            asm volatile("bar.sync 1, 128;" ::: "memory");
            if (tid == 0) mbar_arrive_rank0(sbase + SM_EPIF(b));
        }
    } else if (wid >= 6) {
        // ---- JIT dequant crews: strips PRE_STRIPS..NSTRIPS-1, 8 warps each ----
        const int gwid = (int)blockIdx.x * 2 + (wid - 6);      // 0..295
        const int sidx = PRE_STRIPS + (gwid >> 3);             // crew's strip
        if (gwid < 8 * (NSTRIPS - PRE_STRIPS)) {               // gwid < 240
            const int off = ((gwid & 7) << 5) + lane;          // 0..255
            const int base = sidx * STRIP_I4;
#pragma unroll 4
            for (int k = 0; k < STRIP_I4 / 256; k++)           // 512 iterations
                dq_store_i4(base + off + k * 256, wp, scales);
            __threadfence();
            if (lane == 0) atomicAdd(&g_ready[sidx], 1u);
        }
    }

    __syncthreads();
    asm volatile("barrier.cluster.arrive.aligned;" ::: "memory");
    asm volatile("barrier.cluster.wait.aligned;" ::: "memory");
    if (wid == 5) {
        asm volatile("tcgen05.dealloc.cta_group::2.sync.aligned.b32 %0, %1;"
                     :: "r"(tmem), "r"(512u));
    }
    asm volatile("barrier.cluster.arrive.aligned;" ::: "memory");
    asm volatile("barrier.cluster.wait.aligned;" ::: "memory");
#endif  // HAS_TCGEN05
}

// ---------------------------------------------------------------------------
// Launch
// ---------------------------------------------------------------------------
typedef CUresult (CUDAAPI *PFN_encodeTiled_local)(
    CUtensorMap*, CUtensorMapDataType, cuuint32_t, void*,
    const cuuint64_t*, const cuuint64_t*, const cuuint32_t*, const cuuint32_t*,
    CUtensorMapInterleave, CUtensorMapSwizzle, CUtensorMapL2promotion,
    CUtensorMapFloatOOBfill);

extern "C" void kernel_launch(void* const* d_in, const int* in_sizes, int n_in,
                              void* d_out, int out_size) {
    const float* x      = (const float*)d_in[0];   // [4,2048,4096] fp32
    const int*   wp     = (const int*)d_in[1];     // [11008,2048] int32 (bytes)
    const float* scales = (const float*)d_in[2];   // [11008,32] fp32
    float* out = (float*)d_out;                    // [4,2048,11008] fp32

    PFN_encodeTiled_local encode = nullptr;
    cudaDriverEntryPointQueryResult qres;
    cudaGetDriverEntryPoint("cuTensorMapEncodeTiled", (void**)&encode,
                            cudaEnableDefault, &qres);
    void *pX = nullptr, *pW = nullptr;
    cudaGetSymbolAddress(&pX, g_X16);
    cudaGetSymbolAddress(&pW, g_W16);

    CUtensorMap tmA, tmB;
    if (encode) {
        cuuint64_t dimsA[2] = {IN_F, M_TOT};
        cuuint64_t strA[1]  = {IN_F * 2};
        cuuint32_t boxA[2]  = {BK, BMC};           // 64 halves (=128B, SW128) x 128 rows
        cuuint32_t es[2]    = {1, 1};
        encode(&tmA, CU_TENSOR_MAP_DATA_TYPE_FLOAT16, 2, pX, dimsA, strA, boxA, es,
               CU_TENSOR_MAP_INTERLEAVE_NONE, CU_TENSOR_MAP_SWIZZLE_128B,
               CU_TENSOR_MAP_L2_PROMOTION_L2_128B, CU_TENSOR_MAP_FLOAT_OOB_FILL_NONE);
        cuuint64_t dimsB[2] = {IN_F, OUT_F};
        cuuint64_t strB[1]  = {IN_F * 2};
        cuuint32_t boxB[2]  = {BK, 128};           // 64 halves x 128 rows (N/2 per CTA)
        encode(&tmB, CU_TENSOR_MAP_DATA_TYPE_FLOAT16, 2, pW, dimsB, strB, boxB, es,
               CU_TENSOR_MAP_INTERLEAVE_NONE, CU_TENSOR_MAP_SWIZZLE_128B,
               CU_TENSOR_MAP_L2_PROMOTION_L2_128B, CU_TENSOR_MAP_FLOAT_OOB_FILL_NONE);
    }

    cudaFuncSetAttribute(gemm_tc_kernel, cudaFuncAttributeMaxDynamicSharedMemorySize,
                         SMEM_TOTAL);
    gemm_tc_kernel<<<dim3(2 * NPAIRS, 1), GEMM_THREADS, SMEM_TOTAL>>>(
        tmA, tmB, (const float4*)x, (const int4*)wp, scales, out);
}